// round 8
// baseline (speedup 1.0000x reference)
#include <cuda_runtime.h>
#include <cstdint>

#define DIM    128
#define LMAX   20
#define EPB    32            // elements per CTA
#define ROWB   512           // bytes per row (128 fp32)
#define WPB    8             // warps per block (256 threads)
#define EPWRP  (EPB / WPB)   // 4 elements per warp

__device__ float g_partials[2048];
__device__ unsigned int g_counter = 0;

__device__ __forceinline__ uint32_t smem_u32(const void* p) {
    return (uint32_t)__cvta_generic_to_shared(p);
}

__device__ __forceinline__ void mbar_wait_parity(uint32_t mbar, uint32_t parity) {
    asm volatile(
        "{\n\t"
        ".reg .pred P;\n\t"
        "WAIT_%=:\n\t"
        "mbarrier.try_wait.parity.acquire.cta.shared::cta.b64 P, [%0], %1, 0x989680;\n\t"
        "@P bra DONE_%=;\n\t"
        "bra WAIT_%=;\n\t"
        "DONE_%=:\n\t"
        "}"
        :: "r"(mbar), "r"(parity) : "memory");
}

__global__ void __launch_bounds__(256) sg_loss_kernel(
    const float* __restrict__ W0,
    const float* __restrict__ W1,
    const int* __restrict__ target,
    const int* __restrict__ context,
    const int* __restrict__ codes,
    const int* __restrict__ lengths,
    float* __restrict__ out,
    int B, int n_nodes)
{
    __shared__ __align__(16) unsigned char rows[EPB * 2 * ROWB];  // 32 KB: [t_row|c_row] per element
    __shared__ __align__(8)  unsigned long long mbar;
    __shared__ int   s_t[EPB], s_c[EPB];
    __shared__ float smem_red[WPB];
    __shared__ bool  is_last;

    const int lane = threadIdx.x & 31;
    const int wid  = threadIdx.x >> 5;
    const int base = blockIdx.x * EPB;
    const uint32_t mb = smem_u32(&mbar);

    // ---- load + clamp this CTA's indices (coalesced), init mbarrier ----
    if (threadIdx.x < EPB) {
        const int i = base + threadIdx.x;
        int t = (i < B) ? target[i]  : 0;
        int c = (i < B) ? context[i] : 0;
        if (t < 0 || t >= n_nodes) t = 0;   // clamp (matches JAX OOB-clip)
        if (c < 0 || c >= n_nodes) c = 0;
        s_t[threadIdx.x] = t;
        s_c[threadIdx.x] = c;
    }
    if (threadIdx.x == 0) {
        asm volatile("mbarrier.init.shared.b64 [%0], 1;" :: "r"(mb) : "memory");
    }
    __syncthreads();   // indices + mbarrier visible to all

    // ---- threads 0..63 each issue one 512B bulk copy (64 copies -> one mbarrier) ----
    if (threadIdx.x == 0) {
        asm volatile("mbarrier.arrive.expect_tx.shared.b64 _, [%0], %1;"
                     :: "r"(mb), "r"((uint32_t)(EPB * 2 * ROWB)) : "memory");
    }
    if (threadIdx.x < 2 * EPB) {
        const int e     = threadIdx.x >> 1;
        const int which = threadIdx.x & 1;          // 0 = target row, 1 = context row
        const float* src = which ? (W1 + (long long)s_c[e] * DIM)
                                 : (W0 + (long long)s_t[e] * DIM);
        const uint32_t dst = smem_u32(rows) + (uint32_t)e * (2 * ROWB) + (uint32_t)which * ROWB;
        asm volatile(
            "cp.async.bulk.shared::cta.global.mbarrier::complete_tx::bytes [%0], [%1], %2, [%3];"
            :: "r"(dst), "l"(src), "r"((uint32_t)ROWB), "r"(mb) : "memory");
    }

    // ---- while copies fly: load codes/lengths for this warp's elements ----
    int   len [EPWRP];
    int   code[EPWRP];
    #pragma unroll
    for (int j = 0; j < EPWRP; ++j) {
        const int e = wid + WPB * j;
        const int i = base + e;
        len [j] = (i < B) ? lengths[i] : 0;
        code[j] = (i < B && lane < LMAX) ? codes[i * LMAX + lane] : 0;
    }

    // ---- wait for all 64 rows, then compute ----
    mbar_wait_parity(mb, 0);

    float acc = 0.0f;
    #pragma unroll
    for (int j = 0; j < EPWRP; ++j) {
        const int e = wid + WPB * j;
        const float4 a = *reinterpret_cast<const float4*>(rows + e * (2 * ROWB)        + lane * 16);
        const float4 b = *reinterpret_cast<const float4*>(rows + e * (2 * ROWB) + ROWB + lane * 16);
        float dot = a.x * b.x + a.y * b.y + a.z * b.z + a.w * b.w;
        #pragma unroll
        for (int o = 16; o > 0; o >>= 1)
            dot += __shfl_xor_sync(0xffffffffu, dot, o);
        if (lane < len[j]) {
            const float sign = 1.0f - 2.0f * (float)code[j];
            const float x = sign * dot;
            // stable log_sigmoid: min(x,0) - log1p(exp(-|x|))
            acc -= fminf(x, 0.0f) - log1pf(__expf(-fabsf(x)));
        }
    }

    // ---- warp + block reduce ----
    #pragma unroll
    for (int o = 16; o > 0; o >>= 1)
        acc += __shfl_xor_sync(0xffffffffu, acc, o);
    if (lane == 0) smem_red[wid] = acc;
    __syncthreads();
    if (threadIdx.x == 0) {
        float s = 0.0f;
        #pragma unroll
        for (int i = 0; i < WPB; ++i) s += smem_red[i];
        g_partials[blockIdx.x] = s;
        __threadfence();
        const unsigned int old = atomicAdd(&g_counter, 1u);
        is_last = (old == gridDim.x - 1);
    }
    __syncthreads();

    // ---- last CTA reduces all partials (deterministic order) ----
    if (is_last) {
        __threadfence();
        const int nb = gridDim.x;
        float v = 0.0f;
        for (int i = threadIdx.x; i < nb; i += blockDim.x)
            v += g_partials[i];
        #pragma unroll
        for (int o = 16; o > 0; o >>= 1)
            v += __shfl_xor_sync(0xffffffffu, v, o);
        __shared__ float smem2[WPB];
        if (lane == 0) smem2[wid] = v;
        __syncthreads();
        if (threadIdx.x == 0) {
            float s = 0.0f;
            #pragma unroll
            for (int i = 0; i < WPB; ++i) s += smem2[i];
            out[0] = s;
            g_counter = 0;   // reset for next graph replay
        }
    }
}

extern "C" void kernel_launch(void* const* d_in, const int* in_sizes, int n_in,
                              void* d_out, int out_size)
{
    const float* W0      = (const float*)d_in[0];
    const float* W1      = (const float*)d_in[1];
    const int*   target  = (const int*)d_in[2];
    const int*   context = (const int*)d_in[3];
    const int*   codes   = (const int*)d_in[4];
    const int*   lengths = (const int*)d_in[5];
    float* out = (float*)d_out;

    const int B = in_sizes[2];                 // 16384
    const int n_nodes = in_sizes[0] / DIM;     // 1,000,000
    int blocks = (B + EPB - 1) / EPB;          // 512
    if (blocks > 2048) blocks = 2048;          // scratch bound

    sg_loss_kernel<<<blocks, 256>>>(W0, W1, target, context, codes, lengths, out, B, n_nodes);
}